// round 10
// baseline (speedup 1.0000x reference)
#include <cuda_runtime.h>
#include <math.h>

#define BH 512
#define BW 512
#define BB 8
#define HW (BH*BW)
#define MAXT 160
#define NTHR 256
#define CHUNK 4096                 // pixels per CTA per class plane (8 rows)
#define NBLK (BB*HW/CHUNK)         // 512 CTAs

__device__ double g_acc[8];          // [cls*4 + {sumNo,cntNo,sumObj,cntObj}]
__device__ unsigned int g_ticket;

__device__ __forceinline__ float ex2f_(float x){ float y; asm("ex2.approx.f32 %0,%1;" : "=f"(y) : "f"(x)); return y; }
__device__ __forceinline__ float lg2f_(float x){ float y; asm("lg2.approx.f32 %0,%1;" : "=f"(y) : "f"(x)); return y; }
__device__ __forceinline__ float rcpf_(float x){ float y; asm("rcp.approx.f32 %0,%1;" : "=f"(y) : "f"(x)); return y; }

__device__ __forceinline__ unsigned smem_u32(const void* p) {
    unsigned a;
    asm("{ .reg .u64 t; cvta.to.shared.u64 t, %1; cvt.u32.u64 %0, t; }" : "=r"(a) : "l"(p));
    return a;
}

// ------------------------------------------------------------------
// One CTA = one 512x8 strip of one image (both class planes).
// TMA bulk-stages 32 KB of pred into SMEM; target prologue overlaps the copy.
// ------------------------------------------------------------------
__global__ __launch_bounds__(NTHR, 4)
void fused_kernel(const float* __restrict__ pred,
                  const float* __restrict__ tgt, int nT,
                  float* __restrict__ out) {
    __shared__ __align__(16) float sp0[CHUNK];   // 16 KB plane 0
    __shared__ __align__(16) float sp1[CHUNK];   // 16 KB plane 1
    __shared__ float sc[2][6][MAXT];
    __shared__ int   nAct[2];
    __shared__ float sred[8][6];
    __shared__ __align__(8) unsigned long long mbar;

    const int tid = threadIdx.x;
    const int b   = blockIdx.x >> 6;
    const int q   = blockIdx.x & 63;             // strip index: rows [8q, 8q+8)
    const float* src0 = pred + (size_t)(2 * b) * HW + q * CHUNK;

    if (tid == 0)
        asm volatile("mbarrier.init.shared.b64 [%0], 1;" :: "r"(smem_u32(&mbar)) : "memory");
    if (tid < 2) nAct[tid] = 0;
    __syncthreads();

    // ---- issue both bulk copies (32 KB in flight, no register pressure) ----
    if (tid == 0) {
        unsigned mb = smem_u32(&mbar);
        asm volatile("mbarrier.arrive.expect_tx.shared.b64 _, [%0], %1;"
                     :: "r"(mb), "r"(2u * CHUNK * 4u) : "memory");
        asm volatile("cp.async.bulk.shared::cta.global.mbarrier::complete_tx::bytes [%0], [%1], %2, [%3];"
                     :: "r"(smem_u32(sp0)), "l"(src0), "r"(CHUNK * 4u), "r"(mb) : "memory");
        asm volatile("cp.async.bulk.shared::cta.global.mbarrier::complete_tx::bytes [%0], [%1], %2, [%3];"
                     :: "r"(smem_u32(sp1)), "l"(src0 + HW), "r"(CHUNK * 4u), "r"(mb) : "memory");
    }

    // ---- target prologue overlaps the TMA: filter for this (batch, strip) ----
    const float gxlo = 0.5f, gxhi = BW - 0.5f;
    const float gylo = q * 8 + 0.5f, gyhi = q * 8 + 7.5f;
    for (int i = tid; i < nT; i += NTHR) {
        const float* t = tgt + i * 7;
        if ((int)t[0] != b) continue;
        int   cls = (int)t[1];
        float cx = t[2] * 0.125f, cy = t[3] * 0.125f;
        float ww = t[4] * 0.125f, hh = t[5] * 0.125f;
        float c = __cosf(t[6]), s = __sinf(t[6]);
        float x =  cx * c + cy * s;
        float y = -cx * s + cy * c;
        float X3 = x - hh * 0.5f, X4 = x + hh * 0.5f;
        float Y3 = y - ww * 0.5f, Y4 = y + ww * 0.5f;
        float vxmin = fminf(c * gxlo, c * gxhi) + fminf(s * gylo, s * gyhi);
        float vxmax = fmaxf(c * gxlo, c * gxhi) + fmaxf(s * gylo, s * gyhi);
        float vymin = fminf(-s * gxlo, -s * gxhi) + fminf(c * gylo, c * gyhi);
        float vymax = fmaxf(-s * gxlo, -s * gxhi) + fmaxf(c * gylo, c * gyhi);
        if (vxmax >= X3 - 0.5f && vxmin <= X4 + 0.5f &&
            vymax >= Y3 - 0.5f && vymin <= Y4 + 0.5f) {
            int p = atomicAdd(&nAct[cls], 1);
            sc[cls][0][p] = c;  sc[cls][1][p] = s;
            sc[cls][2][p] = X3; sc[cls][3][p] = X4;
            sc[cls][4][p] = Y3; sc[cls][5][p] = Y4;
        }
    }
    __syncthreads();
    const int n0 = nAct[0], n1 = nAct[1];
    const bool hasT = (n0 | n1) != 0;

    // ---- wait for TMA completion (acquire) ----
    {
        unsigned mb = smem_u32(&mbar);
        unsigned done;
        asm volatile(
            "{\n\t.reg .pred p;\n\t"
            "mbarrier.try_wait.parity.acquire.cta.shared::cta.b64 p, [%1], 0;\n\t"
            "selp.b32 %0, 1, 0, p;\n\t}"
            : "=r"(done) : "r"(mb) : "memory");
        if (!done) {
            asm volatile(
                "{\n\t.reg .pred P1;\n\t"
                "WL_%=:\n\t"
                "mbarrier.try_wait.parity.acquire.cta.shared::cta.b64 P1, [%0], 0, 0x989680;\n\t"
                "@P1 bra.uni WD_%=;\n\t"
                "bra.uni WL_%=;\n\t"
                "WD_%=:\n\t}"
                :: "r"(mb) : "memory");
        }
    }

    const float LOG2E = 1.4426950408889634f;
    const float LN2   = 0.6931471805599453f;
    float* hout = out + 1 + (size_t)b * HW + q * CHUNK;

    float a0 = 0.f, o0 = 0.f, a1 = 0.f, o1 = 0.f;
    unsigned nc = 0u, oc = 0u;   // 16-bit fields [cls0 | cls1<<16], per-lane <=16

    #pragma unroll
    for (int g = 0; g < 4; g++) {
        const int idx = g * 1024 + tid * 4;        // px within chunk
        const float4 F0 = *(const float4*)(sp0 + idx);
        const float4 F1 = *(const float4*)(sp1 + idx);
        float xl0[4] = {F0.x * LOG2E, F0.y * LOG2E, F0.z * LOG2E, F0.w * LOG2E};
        float xl1[4] = {F1.x * LOG2E, F1.y * LOG2E, F1.z * LOG2E, F1.w * LOG2E};
        float t0[4], t1[4];
        #pragma unroll
        for (int k = 0; k < 4; k++) { t0[k] = ex2f_(xl0[k]); t1[k] = ex2f_(xl1[k]); }

        // ---- masks over active lists ----
        unsigned m0 = 0, m1 = 0;   // bits: obj=k, out=4+k
        if (hasT) {
            const float gy  = q * 8 + (idx >> 9) + 0.5f;
            const float gx0 = (idx & 511) + 0.5f;
            for (int j = 0; j < n0; j++) {
                float c  = sc[0][0][j], s  = sc[0][1][j];
                float X3 = sc[0][2][j], X4 = sc[0][3][j];
                float Y3 = sc[0][4][j], Y4 = sc[0][5][j];
                float sgy = s * gy, cgy = c * gy;
                #pragma unroll
                for (int k = 0; k < 4; k++) {
                    float gx = gx0 + (float)k;
                    float vx = fmaf(c, gx, sgy);
                    float vy = fmaf(-s, gx, cgy);
                    unsigned in_ = (vx >= X3) & (vx <= X4) & (vy >= Y3) & (vy <= Y4);
                    unsigned ot_ = (vx >= X3 - 0.5f) & (vx <= X4 + 0.5f) &
                                   (vy >= Y3 - 0.5f) & (vy <= Y4 + 0.5f);
                    m0 |= (in_ << k) | (ot_ << (4 + k));
                }
            }
            for (int j = 0; j < n1; j++) {
                float c  = sc[1][0][j], s  = sc[1][1][j];
                float X3 = sc[1][2][j], X4 = sc[1][3][j];
                float Y3 = sc[1][4][j], Y4 = sc[1][5][j];
                float sgy = s * gy, cgy = c * gy;
                #pragma unroll
                for (int k = 0; k < 4; k++) {
                    float gx = gx0 + (float)k;
                    float vx = fmaf(c, gx, sgy);
                    float vy = fmaf(-s, gx, cgy);
                    unsigned in_ = (vx >= X3) & (vx <= X4) & (vy >= Y3) & (vy <= Y4);
                    unsigned ot_ = (vx >= X3 - 0.5f) & (vx <= X4 + 0.5f) &
                                   (vy >= Y3 - 0.5f) & (vy <= Y4 + 0.5f);
                    m1 |= (in_ << k) | (ot_ << (4 + k));
                }
            }
        }

        // ---- heatmap: batched reciprocal (1 RCP / 4 px); scalar stores ----
        float tm[4], d[4];
        #pragma unroll
        for (int k = 0; k < 4; k++) { tm[k] = fmaxf(t0[k], t1[k]); d[k] = 1.0f + tm[k]; }
        float p01 = d[0] * d[1], p23 = d[2] * d[3];
        float R   = rcpf_(p01 * p23);
        float r01 = R * p23, r23 = R * p01;
        float* hp = hout + idx;
        hp[0] = tm[0] * (r01 * d[1]);
        hp[1] = tm[1] * (r01 * d[0]);
        hp[2] = tm[2] * (r23 * d[3]);
        hp[3] = tm[3] * (r23 * d[2]);

        if ((m0 | m1) == 0u) {
            // pure noobj group: 1 LG2 per class for 4 px
            float P0 = (1.0f + t0[0]) * (1.0f + t0[1]) * (1.0f + t0[2]) * (1.0f + t0[3]);
            float P1 = (1.0f + t1[0]) * (1.0f + t1[1]) * (1.0f + t1[2]) * (1.0f + t1[3]);
            a0 += lg2f_(P0);
            a1 += lg2f_(P1);
            nc += 4u | (4u << 16);
        } else {
            #pragma unroll
            for (int k = 0; k < 4; k++) {
                float L0 = lg2f_(1.0f + t0[k]);
                float L1 = lg2f_(1.0f + t1[k]);
                unsigned ob0 =  (m0 >> k) & 1u;
                unsigned no0 = ((~m0) >> (4 + k)) & 1u;
                unsigned ob1 =  (m1 >> k) & 1u;
                unsigned no1 = ((~m1) >> (4 + k)) & 1u;
                if (no0) a0 += L0;
                if (ob0) o0 += L0 - xl0[k];
                if (no1) a1 += L1;
                if (ob1) o1 += L1 - xl1[k];
                nc += no0 | (no1 << 16);
                oc += ob0 | (ob1 << 16);
            }
        }
    }

    // ---- block reduction: floats via shuffle, counts via REDUX ----
    #pragma unroll
    for (int off = 16; off; off >>= 1) {
        a0 += __shfl_down_sync(0xffffffffu, a0, off);
        o0 += __shfl_down_sync(0xffffffffu, o0, off);
        a1 += __shfl_down_sync(0xffffffffu, a1, off);
        o1 += __shfl_down_sync(0xffffffffu, o1, off);
    }
    nc = __reduce_add_sync(0xffffffffu, nc);
    oc = __reduce_add_sync(0xffffffffu, oc);
    const int wid = tid >> 5;
    if ((tid & 31) == 0) {
        sred[wid][0] = a0; sred[wid][1] = o0;
        sred[wid][2] = a1; sred[wid][3] = o1;
        sred[wid][4] = __uint_as_float(nc);
        sred[wid][5] = __uint_as_float(oc);
    }
    __syncthreads();
    if (tid < 4) {
        float ssum = 0.f;
        #pragma unroll
        for (int wv = 0; wv < 8; wv++) ssum += sred[wv][tid];
        if (ssum != 0.f) atomicAdd(&g_acc[tid * 2], (double)(ssum * LN2));
    } else if (tid == 4) {
        unsigned cNo0 = 0, cNo1 = 0;
        #pragma unroll
        for (int wv = 0; wv < 8; wv++) {
            unsigned cw = __float_as_uint(sred[wv][4]);
            cNo0 += cw & 0xffffu; cNo1 += cw >> 16;
        }
        if (cNo0) atomicAdd(&g_acc[1], (double)cNo0);
        if (cNo1) atomicAdd(&g_acc[5], (double)cNo1);
    } else if (tid == 5) {
        unsigned cOb0 = 0, cOb1 = 0;
        #pragma unroll
        for (int wv = 0; wv < 8; wv++) {
            unsigned cw = __float_as_uint(sred[wv][5]);
            cOb0 += cw & 0xffffu; cOb1 += cw >> 16;
        }
        if (cOb0) atomicAdd(&g_acc[3], (double)cOb0);
        if (cOb1) atomicAdd(&g_acc[7], (double)cOb1);
    }
    if (tid < 6) __threadfence();
    __syncthreads();

    // ---- last-block election: finalize scalar loss, self-clean ----
    if (tid == 0) {
        unsigned int ticket = atomicAdd(&g_ticket, 1u);
        if (ticket == NBLK - 1) {
            __threadfence();
            double a[8];
            #pragma unroll
            for (int j = 0; j < 8; j++)
                a[j] = *((volatile double*)&g_acc[j]);
            double loss = 0.0;
            #pragma unroll
            for (int cls = 0; cls < 2; cls++) {
                double sNo = a[cls * 4 + 0], cNo = a[cls * 4 + 1];
                double sOb = a[cls * 4 + 2], cOb = a[cls * 4 + 3];
                if (cOb > 0.0)
                    loss += sOb / fmax(cOb, 1.0) + sNo / fmax(cNo, 1.0);
            }
            out[0] = (float)loss;
            #pragma unroll
            for (int j = 0; j < 8; j++) g_acc[j] = 0.0;
            g_ticket = 0u;
            __threadfence();
        }
    }
}

// ------------------------------------------------------------------
extern "C" void kernel_launch(void* const* d_in, const int* in_sizes, int n_in,
                              void* d_out, int out_size) {
    const float* pred = (const float*)d_in[0];
    const float* tgt  = (const float*)d_in[1];
    int nT = in_sizes[1] / 7;
    float* out = (float*)d_out;

    fused_kernel<<<NBLK, NTHR>>>(pred, tgt, nT, out);
}

// round 11
// speedup vs baseline: 1.6829x; 1.6829x over previous
#include <cuda_runtime.h>
#include <math.h>

#define BH 512
#define BW 512
#define BB 8
#define HW (BH*BW)
#define NTHR 256

// ---- device scratch (static zero-init; kernels self-clean for graph replay) ----
// per class (stride 5): {S_all, S_out, S_objAdj, cnt_out, cnt_obj}   (log2 domain)
__device__ double g_acc[10];
__device__ unsigned int g_ticket;
__device__ unsigned int g_mask[BB*HW/4];   // 1 byte/px: bit0=obj0,1=out0,2=obj1,3=out1

__device__ __forceinline__ float ex2f_(float x){ float y; asm("ex2.approx.f32 %0,%1;" : "=f"(y) : "f"(x)); return y; }
__device__ __forceinline__ float lg2f_(float x){ float y; asm("lg2.approx.f32 %0,%1;" : "=f"(y) : "f"(x)); return y; }
__device__ __forceinline__ float rcpf_(float x){ float y; asm("rcp.approx.f32 %0,%1;" : "=f"(y) : "f"(x)); return y; }

// ------------------------------------------------------------------
// Kernel A: one block per target; set obj/outer bits in g_mask.
// ------------------------------------------------------------------
__global__ __launch_bounds__(NTHR)
void stamp_kernel(const float* __restrict__ tgt, int nT) {
    const int j = blockIdx.x;
    if (j >= nT) return;
    const float* t = tgt + j * 7;
    const int b   = (int)t[0];
    const int cls = (int)t[1];
    float cx = t[2] * 0.125f, cy = t[3] * 0.125f;
    float ww = t[4] * 0.125f, hh = t[5] * 0.125f;
    float c = __cosf(t[6]), s = __sinf(t[6]);
    float x =  cx * c + cy * s;
    float y = -cx * s + cy * c;
    const float X3 = x - hh * 0.5f, X4 = x + hh * 0.5f;
    const float Y3 = y - ww * 0.5f, Y4 = y + ww * 0.5f;
    const float X1 = X3 - 0.5f, X2 = X4 + 0.5f;
    const float Y1 = Y3 - 0.5f, Y2 = Y4 + 0.5f;

    float gxmin = 1e30f, gxmax = -1e30f, gymin = 1e30f, gymax = -1e30f;
    #pragma unroll
    for (int k = 0; k < 4; k++) {
        float vx = (k & 1) ? X2 : X1;
        float vy = (k & 2) ? Y2 : Y1;
        float gx = c * vx - s * vy;
        float gy = s * vx + c * vy;
        gxmin = fminf(gxmin, gx); gxmax = fmaxf(gxmax, gx);
        gymin = fminf(gymin, gy); gymax = fmaxf(gymax, gy);
    }
    int ix0 = max(0, (int)floorf(gxmin - 0.5f));
    int ix1 = min(BW - 1, (int)ceilf(gxmax - 0.5f) + 1);
    int iy0 = max(0, (int)floorf(gymin - 0.5f));
    int iy1 = min(BH - 1, (int)ceilf(gymax - 0.5f) + 1);
    int Wr = ix1 - ix0 + 1, Hr = iy1 - iy0 + 1;
    if (Wr <= 0 || Hr <= 0) return;

    const unsigned shbase = (unsigned)cls * 2u;
    for (int idx = threadIdx.x; idx < Wr * Hr; idx += NTHR) {
        int ix = ix0 + idx % Wr;
        int iy = iy0 + idx / Wr;
        float gx = ix + 0.5f, gy = iy + 0.5f;
        float vx = fmaf(c, gx, s * gy);
        float vy = fmaf(-s, gx, c * gy);
        bool outer = (vx >= X1) & (vx <= X2) & (vy >= Y1) & (vy <= Y2);
        if (outer) {
            bool inner = (vx >= X3) & (vx <= X4) & (vy >= Y3) & (vy <= Y4);
            unsigned p = (unsigned)b * HW + (unsigned)iy * BW + (unsigned)ix;
            unsigned bits = ((inner ? 1u : 0u) | 2u) << shbase;
            atomicOr(&g_mask[p >> 2], bits << ((p & 3u) * 8u));
        }
    }
}

// ------------------------------------------------------------------
// Kernel B: pure unconditional stream. 2048 blocks x 256 thr x 4 px.
// No masks, no prologue, no pre-compute barriers.
// ------------------------------------------------------------------
__global__ __launch_bounds__(NTHR)
void main_kernel(const float* __restrict__ pred, float* __restrict__ out) {
    __shared__ float sred[8][2];
    const int tid = threadIdx.x;
    const int gp  = blockIdx.x * 1024 + tid * 4;   // global pixel in [0, BB*HW)
    const int b   = gp >> 18;                       // HW = 2^18

    const float* p0 = pred + (size_t)gp + (size_t)b * HW;   // pred[2b*HW + off]
    const float4 F0 = *(const float4*)p0;
    const float4 F1 = *(const float4*)(p0 + HW);

    const float LOG2E = 1.4426950408889634f;
    float xl0[4] = {F0.x * LOG2E, F0.y * LOG2E, F0.z * LOG2E, F0.w * LOG2E};
    float xl1[4] = {F1.x * LOG2E, F1.y * LOG2E, F1.z * LOG2E, F1.w * LOG2E};
    float d0[4], d1[4], tm[4], dm[4];
    #pragma unroll
    for (int k = 0; k < 4; k++) {
        float t0 = ex2f_(xl0[k]);
        float t1 = ex2f_(xl1[k]);
        d0[k] = 1.0f + t0;
        d1[k] = 1.0f + t1;
        tm[k] = fmaxf(t0, t1);
        dm[k] = 1.0f + tm[k];
    }
    // unconditional per-class log-sums: 1 LG2 per class per 4 px
    float a0 = lg2f_((d0[0] * d0[1]) * (d0[2] * d0[3]));
    float a1 = lg2f_((d1[0] * d1[1]) * (d1[2] * d1[3]));

    // heatmap: batched reciprocal (1 RCP per 4 px); scalar stores (out+1 misaligned)
    float p01 = dm[0] * dm[1], p23 = dm[2] * dm[3];
    float R   = rcpf_(p01 * p23);
    float r01 = R * p23, r23 = R * p01;
    float* hp = out + 1 + gp;
    hp[0] = tm[0] * (r01 * dm[1]);
    hp[1] = tm[1] * (r01 * dm[0]);
    hp[2] = tm[2] * (r23 * dm[3]);
    hp[3] = tm[3] * (r23 * dm[2]);

    // block reduction of 2 floats -> 2 double atomics
    #pragma unroll
    for (int off = 16; off; off >>= 1) {
        a0 += __shfl_down_sync(0xffffffffu, a0, off);
        a1 += __shfl_down_sync(0xffffffffu, a1, off);
    }
    const int wid = tid >> 5;
    if ((tid & 31) == 0) { sred[wid][0] = a0; sred[wid][1] = a1; }
    __syncthreads();
    if (tid < 2) {
        float ssum = 0.f;
        #pragma unroll
        for (int wv = 0; wv < 8; wv++) ssum += sred[wv][tid];
        atomicAdd(&g_acc[tid * 5], (double)ssum);   // S_all per class
    }
}

// ------------------------------------------------------------------
// Kernel C: corrections over target bboxes + final scalar.
// atomicAnd-clear gives exact union dedupe and replay self-cleaning.
// ------------------------------------------------------------------
__global__ __launch_bounds__(NTHR)
void corr_kernel(const float* __restrict__ pred,
                 const float* __restrict__ tgt, int nT,
                 float* __restrict__ out) {
    __shared__ float sred[8][4];
    const int tid = threadIdx.x;
    const int j = blockIdx.x;
    const float LOG2E = 1.4426950408889634f;
    const float LN2   = 0.6931471805599453f;

    if (j < nT) {
        const float* t = tgt + j * 7;
        const int b   = (int)t[0];
        const int cls = (int)t[1];
        float cx = t[2] * 0.125f, cy = t[3] * 0.125f;
        float ww = t[4] * 0.125f, hh = t[5] * 0.125f;
        float c = __cosf(t[6]), s = __sinf(t[6]);
        float x =  cx * c + cy * s;
        float y = -cx * s + cy * c;
        const float X3 = x - hh * 0.5f, X4 = x + hh * 0.5f;
        const float Y3 = y - ww * 0.5f, Y4 = y + ww * 0.5f;
        const float X1 = X3 - 0.5f, X2 = X4 + 0.5f;
        const float Y1 = Y3 - 0.5f, Y2 = Y4 + 0.5f;

        float gxmin = 1e30f, gxmax = -1e30f, gymin = 1e30f, gymax = -1e30f;
        #pragma unroll
        for (int k = 0; k < 4; k++) {
            float vx = (k & 1) ? X2 : X1;
            float vy = (k & 2) ? Y2 : Y1;
            float gx = c * vx - s * vy;
            float gy = s * vx + c * vy;
            gxmin = fminf(gxmin, gx); gxmax = fmaxf(gxmax, gx);
            gymin = fminf(gymin, gy); gymax = fmaxf(gymax, gy);
        }
        int ix0 = max(0, (int)floorf(gxmin - 0.5f));
        int ix1 = min(BW - 1, (int)ceilf(gxmax - 0.5f) + 1);
        int iy0 = max(0, (int)floorf(gymin - 0.5f));
        int iy1 = min(BH - 1, (int)ceilf(gymax - 0.5f) + 1);
        int Wr = ix1 - ix0 + 1, Hr = iy1 - iy0 + 1;

        float s_out = 0.f, s_obj = 0.f, c_out = 0.f, c_obj = 0.f;
        if (Wr > 0 && Hr > 0) {
            const float* plane = pred + (size_t)(2 * b + cls) * HW;
            for (int idx = tid; idx < Wr * Hr; idx += NTHR) {
                int ix = ix0 + idx % Wr;
                int iy = iy0 + idx / Wr;
                unsigned p = (unsigned)b * HW + (unsigned)iy * BW + (unsigned)ix;
                unsigned sh = (p & 3u) * 8u + (unsigned)cls * 2u;
                unsigned old = atomicAnd(&g_mask[p >> 2], ~(3u << sh));
                unsigned o = (old >> sh) & 3u;      // bit0=obj, bit1=outer
                if (o & 2u) {                        // first clearer accounts it
                    float xv = plane[(unsigned)iy * BW + (unsigned)ix];
                    float xl = xv * LOG2E;
                    float L  = lg2f_(1.0f + ex2f_(xl));
                    s_out += L;  c_out += 1.f;
                    if (o & 1u) { s_obj += L - xl; c_obj += 1.f; }
                }
            }
        }
        // block reduce 4 values
        #pragma unroll
        for (int off = 16; off; off >>= 1) {
            s_out += __shfl_down_sync(0xffffffffu, s_out, off);
            s_obj += __shfl_down_sync(0xffffffffu, s_obj, off);
            c_out += __shfl_down_sync(0xffffffffu, c_out, off);
            c_obj += __shfl_down_sync(0xffffffffu, c_obj, off);
        }
        const int wid = tid >> 5;
        if ((tid & 31) == 0) {
            sred[wid][0] = s_out; sred[wid][1] = s_obj;
            sred[wid][2] = c_out; sred[wid][3] = c_obj;
        }
        __syncthreads();
        if (tid == 0) {
            float v0 = 0.f, v1 = 0.f, v2 = 0.f, v3 = 0.f;
            #pragma unroll
            for (int wv = 0; wv < 8; wv++) {
                v0 += sred[wv][0]; v1 += sred[wv][1];
                v2 += sred[wv][2]; v3 += sred[wv][3];
            }
            int base = cls * 5;
            if (v0 != 0.f) atomicAdd(&g_acc[base + 1], (double)v0);
            if (v1 != 0.f) atomicAdd(&g_acc[base + 2], (double)v1);
            if (v2 != 0.f) atomicAdd(&g_acc[base + 3], (double)v2);
            if (v3 != 0.f) atomicAdd(&g_acc[base + 4], (double)v3);
        }
    } else {
        __syncthreads();   // keep block shape uniform
    }

    // ---- last-block election: finalize scalar loss, self-clean ----
    if (tid == 0) {
        __threadfence();
        unsigned int ticket = atomicAdd(&g_ticket, 1u);
        if (ticket == gridDim.x - 1) {
            __threadfence();
            double a[10];
            #pragma unroll
            for (int k = 0; k < 10; k++) a[k] = *((volatile double*)&g_acc[k]);
            double loss = 0.0;
            #pragma unroll
            for (int cls = 0; cls < 2; cls++) {
                double S_all = a[cls * 5 + 0];
                double S_out = a[cls * 5 + 1];
                double S_obj = a[cls * 5 + 2];
                double c_out = a[cls * 5 + 3];
                double c_obj = a[cls * 5 + 4];
                double n_no  = (double)BB * HW - c_out;
                if (c_obj > 0.0)
                    loss += LN2 * (S_obj / fmax(c_obj, 1.0) +
                                   (S_all - S_out) / fmax(n_no, 1.0));
            }
            out[0] = (float)loss;
            #pragma unroll
            for (int k = 0; k < 10; k++) g_acc[k] = 0.0;
            g_ticket = 0u;
            __threadfence();
        }
    }
}

// ------------------------------------------------------------------
extern "C" void kernel_launch(void* const* d_in, const int* in_sizes, int n_in,
                              void* d_out, int out_size) {
    const float* pred = (const float*)d_in[0];
    const float* tgt  = (const float*)d_in[1];
    int nT = in_sizes[1] / 7;
    float* out = (float*)d_out;

    if (nT > 0) stamp_kernel<<<nT, NTHR>>>(tgt, nT);
    main_kernel<<<(BB * HW) / 1024, NTHR>>>(pred, out);
    corr_kernel<<<(nT > 0 ? nT : 1), NTHR>>>(pred, tgt, nT, out);
}

// round 12
// speedup vs baseline: 1.9067x; 1.1330x over previous
#include <cuda_runtime.h>
#include <math.h>

#define BH 512
#define BW 512
#define BB 8
#define HW (BH*BW)
#define NTHR 256
#define NSTREAM ((BB*HW)/1024)     // 2048 stream blocks
#define MAXT 160

// ---- device scratch (static zero-init; kernel self-cleans for graph replay) ----
// per class (stride 5): {S_all, S_out, S_objAdj, cnt_out, cnt_obj}  (log2 domain)
__device__ double g_acc[10];
__device__ unsigned int g_ticket;

__device__ __forceinline__ float ex2f_(float x){ float y; asm("ex2.approx.f32 %0,%1;" : "=f"(y) : "f"(x)); return y; }
__device__ __forceinline__ float lg2f_(float x){ float y; asm("lg2.approx.f32 %0,%1;" : "=f"(y) : "f"(x)); return y; }
__device__ __forceinline__ float rcpf_(float x){ float y; asm("rcp.approx.f32 %0,%1;" : "=f"(y) : "f"(x)); return y; }

// decode target i -> rotation + inner rect + image-space bbox of outer rect
__device__ __forceinline__ void decode_target(const float* __restrict__ t,
        int& b, int& cls, float& c, float& s,
        float& X3, float& X4, float& Y3, float& Y4,
        int& ix0, int& ix1, int& iy0, int& iy1) {
    b   = (int)t[0];
    cls = (int)t[1];
    float cx = t[2] * 0.125f, cy = t[3] * 0.125f;
    float ww = t[4] * 0.125f, hh = t[5] * 0.125f;
    c = __cosf(t[6]); s = __sinf(t[6]);
    float x =  cx * c + cy * s;
    float y = -cx * s + cy * c;
    X3 = x - hh * 0.5f; X4 = x + hh * 0.5f;
    Y3 = y - ww * 0.5f; Y4 = y + ww * 0.5f;
    const float X1 = X3 - 0.5f, X2 = X4 + 0.5f;
    const float Y1 = Y3 - 0.5f, Y2 = Y4 + 0.5f;
    float gxmin = 1e30f, gxmax = -1e30f, gymin = 1e30f, gymax = -1e30f;
    #pragma unroll
    for (int k = 0; k < 4; k++) {
        float vx = (k & 1) ? X2 : X1;
        float vy = (k & 2) ? Y2 : Y1;
        float gx = c * vx - s * vy;
        float gy = s * vx + c * vy;
        gxmin = fminf(gxmin, gx); gxmax = fmaxf(gxmax, gx);
        gymin = fminf(gymin, gy); gymax = fmaxf(gymax, gy);
    }
    ix0 = max(0, (int)floorf(gxmin - 0.5f));
    ix1 = min(BW - 1, (int)ceilf(gxmax - 0.5f) + 1);
    iy0 = max(0, (int)floorf(gymin - 0.5f));
    iy1 = min(BH - 1, (int)ceilf(gymax - 0.5f) + 1);
}

// ------------------------------------------------------------------
// Single launch: blocks [0, NSTREAM) = unconditional stream;
// blocks [NSTREAM, NSTREAM+nT) = per-target correction (geometric dedupe).
// ------------------------------------------------------------------
__global__ __launch_bounds__(NTHR)
void fused_kernel(const float* __restrict__ pred,
                  const float* __restrict__ tgt, int nT,
                  float* __restrict__ out) {
    __shared__ float pc[6][MAXT];     // predecessor list: c,s,X3,X4,Y3,Y4
    __shared__ int   nPred;
    __shared__ float sred[8][4];

    const int tid = threadIdx.x;
    const float LOG2E = 1.4426950408889634f;
    const float LN2   = 0.6931471805599453f;

    if (blockIdx.x < NSTREAM) {
        // ================= STREAM: pure unconditional =================
        const int gp = blockIdx.x * 1024 + tid * 4;
        const int b  = gp >> 18;                         // HW = 2^18
        const float* p0 = pred + (size_t)gp + (size_t)b * HW;
        const float4 F0 = *(const float4*)p0;
        const float4 F1 = *(const float4*)(p0 + HW);

        float xl0[4] = {F0.x * LOG2E, F0.y * LOG2E, F0.z * LOG2E, F0.w * LOG2E};
        float xl1[4] = {F1.x * LOG2E, F1.y * LOG2E, F1.z * LOG2E, F1.w * LOG2E};
        float d0[4], d1[4], tm[4], dm[4];
        #pragma unroll
        for (int k = 0; k < 4; k++) {
            float t0 = ex2f_(xl0[k]);
            float t1 = ex2f_(xl1[k]);
            d0[k] = 1.0f + t0;
            d1[k] = 1.0f + t1;
            tm[k] = fmaxf(t0, t1);
            dm[k] = 1.0f + tm[k];
        }
        float a0 = lg2f_((d0[0] * d0[1]) * (d0[2] * d0[3]));
        float a1 = lg2f_((d1[0] * d1[1]) * (d1[2] * d1[3]));

        float p01 = dm[0] * dm[1], p23 = dm[2] * dm[3];
        float R   = rcpf_(p01 * p23);
        float r01 = R * p23, r23 = R * p01;
        float* hp = out + 1 + gp;
        hp[0] = tm[0] * (r01 * dm[1]);
        hp[1] = tm[1] * (r01 * dm[0]);
        hp[2] = tm[2] * (r23 * dm[3]);
        hp[3] = tm[3] * (r23 * dm[2]);

        #pragma unroll
        for (int off = 16; off; off >>= 1) {
            a0 += __shfl_down_sync(0xffffffffu, a0, off);
            a1 += __shfl_down_sync(0xffffffffu, a1, off);
        }
        const int wid = tid >> 5;
        if ((tid & 31) == 0) { sred[wid][0] = a0; sred[wid][1] = a1; }
        __syncthreads();
        if (tid < 2) {
            float ssum = 0.f;
            #pragma unroll
            for (int wv = 0; wv < 8; wv++) ssum += sred[wv][tid];
            atomicAdd(&g_acc[tid * 5], (double)ssum);   // S_all per class
            __threadfence();
        }
    } else {
        // ================= CORRECTION: target j =================
        const int j = blockIdx.x - NSTREAM;
        int b, cls, ix0, ix1, iy0, iy1;
        float c, s, X3, X4, Y3, Y4;
        decode_target(tgt + j * 7, b, cls, c, s, X3, X4, Y3, Y4, ix0, ix1, iy0, iy1);

        if (tid == 0) nPred = 0;
        __syncthreads();

        // predecessors i<j, same (b,cls), intersecting bbox
        for (int i = tid; i < j; i += NTHR) {
            int bi, ci_, jx0, jx1, jy0, jy1;
            float cI, sI, A3, A4, B3, B4;
            decode_target(tgt + i * 7, bi, ci_, cI, sI, A3, A4, B3, B4, jx0, jx1, jy0, jy1);
            if (bi != b || ci_ != cls) continue;
            if (jx1 < ix0 || jx0 > ix1 || jy1 < iy0 || jy0 > iy1) continue;
            int p = atomicAdd(&nPred, 1);
            pc[0][p] = cI; pc[1][p] = sI;
            pc[2][p] = A3; pc[3][p] = A4;
            pc[4][p] = B3; pc[5][p] = B4;
        }
        __syncthreads();
        const int np = nPred;

        float s_out = 0.f, s_obj = 0.f, c_out = 0.f, c_obj = 0.f;
        const int Wr = ix1 - ix0 + 1, Hr = iy1 - iy0 + 1;
        if (Wr > 0 && Hr > 0) {
            const float* plane = pred + (size_t)(2 * b + cls) * HW;
            for (int idx = tid; idx < Wr * Hr; idx += NTHR) {
                int ix = ix0 + idx % Wr;
                int iy = iy0 + idx / Wr;
                float gx = ix + 0.5f, gy = iy + 0.5f;
                float vx = fmaf(c, gx, s * gy);
                float vy = fmaf(-s, gx, c * gy);
                bool outer = (vx >= X3 - 0.5f) & (vx <= X4 + 0.5f) &
                             (vy >= Y3 - 0.5f) & (vy <= Y4 + 0.5f);
                if (!outer) continue;
                bool inner = (vx >= X3) & (vx <= X4) & (vy >= Y3) & (vy <= Y4);

                bool prevOut = false, prevIn = false;
                for (int p = 0; p < np; p++) {
                    float cI = pc[0][p], sI = pc[1][p];
                    float A3 = pc[2][p], A4 = pc[3][p];
                    float B3 = pc[4][p], B4 = pc[5][p];
                    float ux = fmaf(cI, gx, sI * gy);
                    float uy = fmaf(-sI, gx, cI * gy);
                    bool oi = (ux >= A3 - 0.5f) & (ux <= A4 + 0.5f) &
                              (uy >= B3 - 0.5f) & (uy <= B4 + 0.5f);
                    bool ii = (ux >= A3) & (ux <= A4) & (uy >= B3) & (uy <= B4);
                    prevOut |= oi; prevIn |= ii;
                }
                bool doOut = !prevOut;
                bool doObj = inner & !prevIn;
                if (doOut | doObj) {
                    float xv = plane[(unsigned)iy * BW + (unsigned)ix];
                    float xl = xv * LOG2E;
                    float L  = lg2f_(1.0f + ex2f_(xl));
                    if (doOut) { s_out += L;      c_out += 1.f; }
                    if (doObj) { s_obj += L - xl; c_obj += 1.f; }
                }
            }
        }
        #pragma unroll
        for (int off = 16; off; off >>= 1) {
            s_out += __shfl_down_sync(0xffffffffu, s_out, off);
            s_obj += __shfl_down_sync(0xffffffffu, s_obj, off);
            c_out += __shfl_down_sync(0xffffffffu, c_out, off);
            c_obj += __shfl_down_sync(0xffffffffu, c_obj, off);
        }
        const int wid = tid >> 5;
        if ((tid & 31) == 0) {
            sred[wid][0] = s_out; sred[wid][1] = s_obj;
            sred[wid][2] = c_out; sred[wid][3] = c_obj;
        }
        __syncthreads();
        if (tid == 0) {
            float v0 = 0.f, v1 = 0.f, v2 = 0.f, v3 = 0.f;
            #pragma unroll
            for (int wv = 0; wv < 8; wv++) {
                v0 += sred[wv][0]; v1 += sred[wv][1];
                v2 += sred[wv][2]; v3 += sred[wv][3];
            }
            int base = cls * 5;
            if (v0 != 0.f) atomicAdd(&g_acc[base + 1], (double)v0);
            if (v1 != 0.f) atomicAdd(&g_acc[base + 2], (double)v1);
            if (v2 != 0.f) atomicAdd(&g_acc[base + 3], (double)v2);
            if (v3 != 0.f) atomicAdd(&g_acc[base + 4], (double)v3);
            __threadfence();
        }
    }
    __syncthreads();

    // ---- last-block election: finalize scalar loss, self-clean ----
    if (tid == 0) {
        unsigned int ticket = atomicAdd(&g_ticket, 1u);
        if (ticket == gridDim.x - 1) {
            __threadfence();
            double a[10];
            #pragma unroll
            for (int k = 0; k < 10; k++) a[k] = *((volatile double*)&g_acc[k]);
            double loss = 0.0;
            #pragma unroll
            for (int cls = 0; cls < 2; cls++) {
                double S_all = a[cls * 5 + 0];
                double S_out = a[cls * 5 + 1];
                double S_obj = a[cls * 5 + 2];
                double cOut  = a[cls * 5 + 3];
                double cObj  = a[cls * 5 + 4];
                double n_no  = (double)BB * HW - cOut;
                if (cObj > 0.0)
                    loss += LN2 * (S_obj / fmax(cObj, 1.0) +
                                   (S_all - S_out) / fmax(n_no, 1.0));
            }
            out[0] = (float)loss;
            #pragma unroll
            for (int k = 0; k < 10; k++) g_acc[k] = 0.0;
            g_ticket = 0u;
            __threadfence();
        }
    }
}

// ------------------------------------------------------------------
extern "C" void kernel_launch(void* const* d_in, const int* in_sizes, int n_in,
                              void* d_out, int out_size) {
    const float* pred = (const float*)d_in[0];
    const float* tgt  = (const float*)d_in[1];
    int nT = in_sizes[1] / 7;
    if (nT > MAXT) nT = MAXT;
    float* out = (float*)d_out;

    fused_kernel<<<NSTREAM + nT, NTHR>>>(pred, tgt, nT, out);
}

// round 13
// speedup vs baseline: 2.3439x; 1.2293x over previous
#include <cuda_runtime.h>
#include <math.h>

#define BH 512
#define BW 512
#define BB 8
#define HW (BH*BW)
#define NTHR 256
#define NSTR 512                   // stream blocks
#define GPI  (NSTR*NTHR)           // groups per iteration slab = 131072
#define MAXT 160

// ---- device scratch (static zero-init; kernel self-cleans for graph replay) ----
// per class (stride 5): {S_all, S_out, S_objAdj, cnt_out, cnt_obj}  (log2 domain)
__device__ double g_acc[10];
__device__ unsigned int g_ticket;

__device__ __forceinline__ float ex2f_(float x){ float y; asm("ex2.approx.f32 %0,%1;" : "=f"(y) : "f"(x)); return y; }
__device__ __forceinline__ float lg2f_(float x){ float y; asm("lg2.approx.f32 %0,%1;" : "=f"(y) : "f"(x)); return y; }
__device__ __forceinline__ float rcpf_(float x){ float y; asm("rcp.approx.f32 %0,%1;" : "=f"(y) : "f"(x)); return y; }

__device__ __forceinline__ void decode_target(const float* __restrict__ t,
        int& b, int& cls, float& c, float& s,
        float& X3, float& X4, float& Y3, float& Y4,
        int& ix0, int& ix1, int& iy0, int& iy1) {
    b   = (int)t[0];
    cls = (int)t[1];
    float cx = t[2] * 0.125f, cy = t[3] * 0.125f;
    float ww = t[4] * 0.125f, hh = t[5] * 0.125f;
    c = __cosf(t[6]); s = __sinf(t[6]);
    float x =  cx * c + cy * s;
    float y = -cx * s + cy * c;
    X3 = x - hh * 0.5f; X4 = x + hh * 0.5f;
    Y3 = y - ww * 0.5f; Y4 = y + ww * 0.5f;
    const float X1 = X3 - 0.5f, X2 = X4 + 0.5f;
    const float Y1 = Y3 - 0.5f, Y2 = Y4 + 0.5f;
    float gxmin = 1e30f, gxmax = -1e30f, gymin = 1e30f, gymax = -1e30f;
    #pragma unroll
    for (int k = 0; k < 4; k++) {
        float vx = (k & 1) ? X2 : X1;
        float vy = (k & 2) ? Y2 : Y1;
        float gx = c * vx - s * vy;
        float gy = s * vx + c * vy;
        gxmin = fminf(gxmin, gx); gxmax = fmaxf(gxmax, gx);
        gymin = fminf(gymin, gy); gymax = fmaxf(gymax, gy);
    }
    ix0 = max(0, (int)floorf(gxmin - 0.5f));
    ix1 = min(BW - 1, (int)ceilf(gxmax - 0.5f) + 1);
    iy0 = max(0, (int)floorf(gymin - 0.5f));
    iy1 = min(BH - 1, (int)ceilf(gymax - 0.5f) + 1);
}

// ------------------------------------------------------------------
// Single launch, single wave: blocks [0,nT) = per-target correction;
// blocks [nT, nT+NSTR) = pipelined unconditional stream (4 groups/thread).
// ------------------------------------------------------------------
__global__ __launch_bounds__(NTHR, 5)
void fused_kernel(const float* __restrict__ pred,
                  const float* __restrict__ tgt, int nT,
                  float* __restrict__ out) {
    __shared__ float pc[6][MAXT];
    __shared__ int   nPred;
    __shared__ float sred[8][4];

    const int tid = threadIdx.x;
    const float LOG2E = 1.4426950408889634f;
    const float LN2   = 0.6931471805599453f;

    if (blockIdx.x >= (unsigned)nT) {
        // ================= STREAM (pipelined) =================
        const int bs  = blockIdx.x - nT;
        const int gid = bs * NTHR + tid;

        float a0 = 0.f, a1 = 0.f;
        // prologue load (iteration 0)
        float4 A0, A1;
        {
            int gp = gid * 4;
            int b  = gp >> 18;
            const float* p = pred + gp + (size_t)b * HW;
            A0 = *(const float4*)p;
            A1 = *(const float4*)(p + HW);
        }
        #pragma unroll
        for (int it = 0; it < 4; it++) {
            float4 B0, B1;
            if (it < 3) {     // prefetch next iteration
                int gp2 = (gid + (it + 1) * GPI) * 4;
                int b2  = gp2 >> 18;
                const float* p2 = pred + gp2 + (size_t)b2 * HW;
                B0 = *(const float4*)p2;
                B1 = *(const float4*)(p2 + HW);
            }
            const int gp = (gid + it * GPI) * 4;
            float xl0[4] = {A0.x * LOG2E, A0.y * LOG2E, A0.z * LOG2E, A0.w * LOG2E};
            float xl1[4] = {A1.x * LOG2E, A1.y * LOG2E, A1.z * LOG2E, A1.w * LOG2E};
            float d0[4], d1[4], tm[4], dm[4];
            #pragma unroll
            for (int k = 0; k < 4; k++) {
                float t0 = ex2f_(xl0[k]);
                float t1 = ex2f_(xl1[k]);
                d0[k] = 1.0f + t0;
                d1[k] = 1.0f + t1;
                tm[k] = fmaxf(t0, t1);
                dm[k] = 1.0f + tm[k];
            }
            a0 += lg2f_((d0[0] * d0[1]) * (d0[2] * d0[3]));
            a1 += lg2f_((d1[0] * d1[1]) * (d1[2] * d1[3]));

            float p01 = dm[0] * dm[1], p23 = dm[2] * dm[3];
            float R   = rcpf_(p01 * p23);
            float r01 = R * p23, r23 = R * p01;
            float* hp = out + 1 + gp;
            hp[0] = tm[0] * (r01 * dm[1]);
            hp[1] = tm[1] * (r01 * dm[0]);
            hp[2] = tm[2] * (r23 * dm[3]);
            hp[3] = tm[3] * (r23 * dm[2]);
            A0 = B0; A1 = B1;
        }

        #pragma unroll
        for (int off = 16; off; off >>= 1) {
            a0 += __shfl_down_sync(0xffffffffu, a0, off);
            a1 += __shfl_down_sync(0xffffffffu, a1, off);
        }
        const int wid = tid >> 5;
        if ((tid & 31) == 0) { sred[wid][0] = a0; sred[wid][1] = a1; }
        __syncthreads();
        if (tid < 2) {
            float ssum = 0.f;
            #pragma unroll
            for (int wv = 0; wv < 8; wv++) ssum += sred[wv][tid];
            atomicAdd(&g_acc[tid * 5], (double)ssum);   // S_all per class
            __threadfence();
        }
    } else {
        // ================= CORRECTION: target j =================
        const int j = blockIdx.x;
        int b, cls, ix0, ix1, iy0, iy1;
        float c, s, X3, X4, Y3, Y4;
        decode_target(tgt + j * 7, b, cls, c, s, X3, X4, Y3, Y4, ix0, ix1, iy0, iy1);

        if (tid == 0) nPred = 0;
        __syncthreads();

        for (int i = tid; i < j; i += NTHR) {
            int bi, ci_, jx0, jx1, jy0, jy1;
            float cI, sI, A3, A4, B3, B4;
            decode_target(tgt + i * 7, bi, ci_, cI, sI, A3, A4, B3, B4, jx0, jx1, jy0, jy1);
            if (bi != b || ci_ != cls) continue;
            if (jx1 < ix0 || jx0 > ix1 || jy1 < iy0 || jy0 > iy1) continue;
            int p = atomicAdd(&nPred, 1);
            pc[0][p] = cI; pc[1][p] = sI;
            pc[2][p] = A3; pc[3][p] = A4;
            pc[4][p] = B3; pc[5][p] = B4;
        }
        __syncthreads();
        const int np = nPred;

        float s_out = 0.f, s_obj = 0.f, c_out = 0.f, c_obj = 0.f;
        const int Wr = ix1 - ix0 + 1, Hr = iy1 - iy0 + 1;
        if (Wr > 0 && Hr > 0) {
            const float* plane = pred + (size_t)(2 * b + cls) * HW;
            for (int idx = tid; idx < Wr * Hr; idx += NTHR) {
                int ix = ix0 + idx % Wr;
                int iy = iy0 + idx / Wr;
                float gx = ix + 0.5f, gy = iy + 0.5f;
                float vx = fmaf(c, gx, s * gy);
                float vy = fmaf(-s, gx, c * gy);
                bool outer = (vx >= X3 - 0.5f) & (vx <= X4 + 0.5f) &
                             (vy >= Y3 - 0.5f) & (vy <= Y4 + 0.5f);
                if (!outer) continue;
                bool inner = (vx >= X3) & (vx <= X4) & (vy >= Y3) & (vy <= Y4);

                bool prevOut = false, prevIn = false;
                for (int p = 0; p < np; p++) {
                    float cI = pc[0][p], sI = pc[1][p];
                    float A3 = pc[2][p], A4 = pc[3][p];
                    float B3 = pc[4][p], B4 = pc[5][p];
                    float ux = fmaf(cI, gx, sI * gy);
                    float uy = fmaf(-sI, gx, cI * gy);
                    bool oi = (ux >= A3 - 0.5f) & (ux <= A4 + 0.5f) &
                              (uy >= B3 - 0.5f) & (uy <= B4 + 0.5f);
                    bool ii = (ux >= A3) & (ux <= A4) & (uy >= B3) & (uy <= B4);
                    prevOut |= oi; prevIn |= ii;
                }
                bool doOut = !prevOut;
                bool doObj = inner & !prevIn;
                if (doOut | doObj) {
                    float xv = plane[(unsigned)iy * BW + (unsigned)ix];
                    float xl = xv * LOG2E;
                    float L  = lg2f_(1.0f + ex2f_(xl));
                    if (doOut) { s_out += L;      c_out += 1.f; }
                    if (doObj) { s_obj += L - xl; c_obj += 1.f; }
                }
            }
        }
        #pragma unroll
        for (int off = 16; off; off >>= 1) {
            s_out += __shfl_down_sync(0xffffffffu, s_out, off);
            s_obj += __shfl_down_sync(0xffffffffu, s_obj, off);
            c_out += __shfl_down_sync(0xffffffffu, c_out, off);
            c_obj += __shfl_down_sync(0xffffffffu, c_obj, off);
        }
        const int wid = tid >> 5;
        if ((tid & 31) == 0) {
            sred[wid][0] = s_out; sred[wid][1] = s_obj;
            sred[wid][2] = c_out; sred[wid][3] = c_obj;
        }
        __syncthreads();
        if (tid == 0) {
            float v0 = 0.f, v1 = 0.f, v2 = 0.f, v3 = 0.f;
            #pragma unroll
            for (int wv = 0; wv < 8; wv++) {
                v0 += sred[wv][0]; v1 += sred[wv][1];
                v2 += sred[wv][2]; v3 += sred[wv][3];
            }
            int base = cls * 5;
            if (v0 != 0.f) atomicAdd(&g_acc[base + 1], (double)v0);
            if (v1 != 0.f) atomicAdd(&g_acc[base + 2], (double)v1);
            if (v2 != 0.f) atomicAdd(&g_acc[base + 3], (double)v2);
            if (v3 != 0.f) atomicAdd(&g_acc[base + 4], (double)v3);
            __threadfence();
        }
    }
    __syncthreads();

    // ---- last-block election: finalize scalar loss, self-clean ----
    if (tid == 0) {
        unsigned int ticket = atomicAdd(&g_ticket, 1u);
        if (ticket == gridDim.x - 1) {
            __threadfence();
            double a[10];
            #pragma unroll
            for (int k = 0; k < 10; k++) a[k] = *((volatile double*)&g_acc[k]);
            double loss = 0.0;
            #pragma unroll
            for (int cls = 0; cls < 2; cls++) {
                double S_all = a[cls * 5 + 0];
                double S_out = a[cls * 5 + 1];
                double S_obj = a[cls * 5 + 2];
                double cOut  = a[cls * 5 + 3];
                double cObj  = a[cls * 5 + 4];
                double n_no  = (double)BB * HW - cOut;
                if (cObj > 0.0)
                    loss += LN2 * (S_obj / fmax(cObj, 1.0) +
                                   (S_all - S_out) / fmax(n_no, 1.0));
            }
            out[0] = (float)loss;
            #pragma unroll
            for (int k = 0; k < 10; k++) g_acc[k] = 0.0;
            g_ticket = 0u;
            __threadfence();
        }
    }
}

// ------------------------------------------------------------------
extern "C" void kernel_launch(void* const* d_in, const int* in_sizes, int n_in,
                              void* d_out, int out_size) {
    const float* pred = (const float*)d_in[0];
    const float* tgt  = (const float*)d_in[1];
    int nT = in_sizes[1] / 7;
    if (nT > MAXT) nT = MAXT;
    float* out = (float*)d_out;

    fused_kernel<<<nT + NSTR, NTHR>>>(pred, tgt, nT, out);
}

// round 14
// speedup vs baseline: 2.3844x; 1.0173x over previous
#include <cuda_runtime.h>
#include <math.h>

#define BH 512
#define BW 512
#define BB 8
#define HW (BH*BW)
#define NTHR 256
#define NSTR 256                   // stream blocks
#define NITER 8                    // iterations per thread
#define GPI  (NSTR*NTHR)           // groups per iteration slab = 65536
#define MAXT 160

// ---- device scratch (static zero-init; kernel self-cleans for graph replay) ----
// per class (stride 5): {S_all, S_out, S_objAdj, cnt_out, cnt_obj}  (log2 domain)
__device__ double g_acc[10];
__device__ unsigned int g_ticket;

__device__ __forceinline__ float ex2f_(float x){ float y; asm("ex2.approx.f32 %0,%1;" : "=f"(y) : "f"(x)); return y; }
__device__ __forceinline__ float lg2f_(float x){ float y; asm("lg2.approx.f32 %0,%1;" : "=f"(y) : "f"(x)); return y; }
__device__ __forceinline__ float rcpf_(float x){ float y; asm("rcp.approx.f32 %0,%1;" : "=f"(y) : "f"(x)); return y; }

__device__ __forceinline__ void decode_target(const float* __restrict__ t,
        int& b, int& cls, float& c, float& s,
        float& X3, float& X4, float& Y3, float& Y4,
        int& ix0, int& ix1, int& iy0, int& iy1) {
    b   = (int)t[0];
    cls = (int)t[1];
    float cx = t[2] * 0.125f, cy = t[3] * 0.125f;
    float ww = t[4] * 0.125f, hh = t[5] * 0.125f;
    c = __cosf(t[6]); s = __sinf(t[6]);
    float x =  cx * c + cy * s;
    float y = -cx * s + cy * c;
    X3 = x - hh * 0.5f; X4 = x + hh * 0.5f;
    Y3 = y - ww * 0.5f; Y4 = y + ww * 0.5f;
    const float X1 = X3 - 0.5f, X2 = X4 + 0.5f;
    const float Y1 = Y3 - 0.5f, Y2 = Y4 + 0.5f;
    float gxmin = 1e30f, gxmax = -1e30f, gymin = 1e30f, gymax = -1e30f;
    #pragma unroll
    for (int k = 0; k < 4; k++) {
        float vx = (k & 1) ? X2 : X1;
        float vy = (k & 2) ? Y2 : Y1;
        float gx = c * vx - s * vy;
        float gy = s * vx + c * vy;
        gxmin = fminf(gxmin, gx); gxmax = fmaxf(gxmax, gx);
        gymin = fminf(gymin, gy); gymax = fmaxf(gymax, gy);
    }
    ix0 = max(0, (int)floorf(gxmin - 0.5f));
    ix1 = min(BW - 1, (int)ceilf(gxmax - 0.5f) + 1);
    iy0 = max(0, (int)floorf(gymin - 0.5f));
    iy1 = min(BH - 1, (int)ceilf(gymax - 0.5f) + 1);
}

// ------------------------------------------------------------------
// Single launch, single wave: blocks [0,nT) = per-target correction;
// blocks [nT, nT+NSTR) = pipelined stream (8 iters/thread, prefetch depth 2).
// ------------------------------------------------------------------
__global__ __launch_bounds__(NTHR, 4)
void fused_kernel(const float* __restrict__ pred,
                  const float* __restrict__ tgt, int nT,
                  float* __restrict__ out) {
    __shared__ float pc[6][MAXT];
    __shared__ int   nPred;
    __shared__ float sred[8][4];

    const int tid = threadIdx.x;
    const float LOG2E = 1.4426950408889634f;
    const float LN2   = 0.6931471805599453f;

    if (blockIdx.x >= (unsigned)nT) {
        // ================= STREAM (8 iters, prefetch depth 2) =================
        const int bs  = blockIdx.x - nT;
        const int gid = bs * NTHR + tid;

        float a0 = 0.f, a1 = 0.f;
        float4 b0[3], b1[3];
        // prologue: load iterations 0 and 1
        #pragma unroll
        for (int pi = 0; pi < 2; pi++) {
            int gp = (gid + pi * GPI) * 4;
            int b  = gp >> 18;
            const float* p = pred + gp + (size_t)b * HW;
            b0[pi] = *(const float4*)p;
            b1[pi] = *(const float4*)(p + HW);
        }
        #pragma unroll
        for (int it = 0; it < NITER; it++) {
            if (it + 2 < NITER) {             // prefetch 2 ahead
                int gp2 = (gid + (it + 2) * GPI) * 4;
                int b2  = gp2 >> 18;
                const float* p2 = pred + gp2 + (size_t)b2 * HW;
                b0[(it + 2) % 3] = *(const float4*)p2;
                b1[(it + 2) % 3] = *(const float4*)(p2 + HW);
            }
            const float4 A0 = b0[it % 3], A1 = b1[it % 3];
            const int gp = (gid + it * GPI) * 4;

            float xl0[4] = {A0.x * LOG2E, A0.y * LOG2E, A0.z * LOG2E, A0.w * LOG2E};
            float xl1[4] = {A1.x * LOG2E, A1.y * LOG2E, A1.z * LOG2E, A1.w * LOG2E};
            float d0[4], d1[4], tm[4], dm[4];
            #pragma unroll
            for (int k = 0; k < 4; k++) {
                float t0 = ex2f_(xl0[k]);
                float t1 = ex2f_(xl1[k]);
                d0[k] = 1.0f + t0;
                d1[k] = 1.0f + t1;
                tm[k] = fmaxf(t0, t1);
                dm[k] = fmaxf(d0[k], d1[k]);   // = 1 + tm
            }
            a0 += lg2f_((d0[0] * d0[1]) * (d0[2] * d0[3]));
            a1 += lg2f_((d1[0] * d1[1]) * (d1[2] * d1[3]));

            float p01 = dm[0] * dm[1], p23 = dm[2] * dm[3];
            float R   = rcpf_(p01 * p23);
            float r01 = R * p23, r23 = R * p01;
            float* hp = out + 1 + gp;
            hp[0] = tm[0] * (r01 * dm[1]);
            hp[1] = tm[1] * (r01 * dm[0]);
            hp[2] = tm[2] * (r23 * dm[3]);
            hp[3] = tm[3] * (r23 * dm[2]);
        }

        #pragma unroll
        for (int off = 16; off; off >>= 1) {
            a0 += __shfl_down_sync(0xffffffffu, a0, off);
            a1 += __shfl_down_sync(0xffffffffu, a1, off);
        }
        const int wid = tid >> 5;
        if ((tid & 31) == 0) { sred[wid][0] = a0; sred[wid][1] = a1; }
        __syncthreads();
        if (tid < 2) {
            float ssum = 0.f;
            #pragma unroll
            for (int wv = 0; wv < 8; wv++) ssum += sred[wv][tid];
            atomicAdd(&g_acc[tid * 5], (double)ssum);   // S_all per class
            __threadfence();
        }
    } else {
        // ================= CORRECTION: target j =================
        const int j = blockIdx.x;
        int b, cls, ix0, ix1, iy0, iy1;
        float c, s, X3, X4, Y3, Y4;
        decode_target(tgt + j * 7, b, cls, c, s, X3, X4, Y3, Y4, ix0, ix1, iy0, iy1);

        if (tid == 0) nPred = 0;
        __syncthreads();

        for (int i = tid; i < j; i += NTHR) {
            int bi, ci_, jx0, jx1, jy0, jy1;
            float cI, sI, A3, A4, B3, B4;
            decode_target(tgt + i * 7, bi, ci_, cI, sI, A3, A4, B3, B4, jx0, jx1, jy0, jy1);
            if (bi != b || ci_ != cls) continue;
            if (jx1 < ix0 || jx0 > ix1 || jy1 < iy0 || jy0 > iy1) continue;
            int p = atomicAdd(&nPred, 1);
            pc[0][p] = cI; pc[1][p] = sI;
            pc[2][p] = A3; pc[3][p] = A4;
            pc[4][p] = B3; pc[5][p] = B4;
        }
        __syncthreads();
        const int np = nPred;

        float s_out = 0.f, s_obj = 0.f, c_out = 0.f, c_obj = 0.f;
        const int Wr = ix1 - ix0 + 1, Hr = iy1 - iy0 + 1;
        if (Wr > 0 && Hr > 0) {
            const float* plane = pred + (size_t)(2 * b + cls) * HW;
            for (int idx = tid; idx < Wr * Hr; idx += NTHR) {
                int ix = ix0 + idx % Wr;
                int iy = iy0 + idx / Wr;
                float gx = ix + 0.5f, gy = iy + 0.5f;
                float vx = fmaf(c, gx, s * gy);
                float vy = fmaf(-s, gx, c * gy);
                bool outer = (vx >= X3 - 0.5f) & (vx <= X4 + 0.5f) &
                             (vy >= Y3 - 0.5f) & (vy <= Y4 + 0.5f);
                if (!outer) continue;
                bool inner = (vx >= X3) & (vx <= X4) & (vy >= Y3) & (vy <= Y4);

                bool prevOut = false, prevIn = false;
                for (int p = 0; p < np; p++) {
                    float cI = pc[0][p], sI = pc[1][p];
                    float A3 = pc[2][p], A4 = pc[3][p];
                    float B3 = pc[4][p], B4 = pc[5][p];
                    float ux = fmaf(cI, gx, sI * gy);
                    float uy = fmaf(-sI, gx, cI * gy);
                    bool oi = (ux >= A3 - 0.5f) & (ux <= A4 + 0.5f) &
                              (uy >= B3 - 0.5f) & (uy <= B4 + 0.5f);
                    bool ii = (ux >= A3) & (ux <= A4) & (uy >= B3) & (uy <= B4);
                    prevOut |= oi; prevIn |= ii;
                }
                bool doOut = !prevOut;
                bool doObj = inner & !prevIn;
                if (doOut | doObj) {
                    float xv = plane[(unsigned)iy * BW + (unsigned)ix];
                    float xl = xv * LOG2E;
                    float L  = lg2f_(1.0f + ex2f_(xl));
                    if (doOut) { s_out += L;      c_out += 1.f; }
                    if (doObj) { s_obj += L - xl; c_obj += 1.f; }
                }
            }
        }
        #pragma unroll
        for (int off = 16; off; off >>= 1) {
            s_out += __shfl_down_sync(0xffffffffu, s_out, off);
            s_obj += __shfl_down_sync(0xffffffffu, s_obj, off);
            c_out += __shfl_down_sync(0xffffffffu, c_out, off);
            c_obj += __shfl_down_sync(0xffffffffu, c_obj, off);
        }
        const int wid = tid >> 5;
        if ((tid & 31) == 0) {
            sred[wid][0] = s_out; sred[wid][1] = s_obj;
            sred[wid][2] = c_out; sred[wid][3] = c_obj;
        }
        __syncthreads();
        if (tid == 0) {
            float v0 = 0.f, v1 = 0.f, v2 = 0.f, v3 = 0.f;
            #pragma unroll
            for (int wv = 0; wv < 8; wv++) {
                v0 += sred[wv][0]; v1 += sred[wv][1];
                v2 += sred[wv][2]; v3 += sred[wv][3];
            }
            int base = cls * 5;
            if (v0 != 0.f) atomicAdd(&g_acc[base + 1], (double)v0);
            if (v1 != 0.f) atomicAdd(&g_acc[base + 2], (double)v1);
            if (v2 != 0.f) atomicAdd(&g_acc[base + 3], (double)v2);
            if (v3 != 0.f) atomicAdd(&g_acc[base + 4], (double)v3);
            __threadfence();
        }
    }
    __syncthreads();

    // ---- last-block election: finalize scalar loss, self-clean ----
    if (tid == 0) {
        unsigned int ticket = atomicAdd(&g_ticket, 1u);
        if (ticket == gridDim.x - 1) {
            __threadfence();
            double a[10];
            #pragma unroll
            for (int k = 0; k < 10; k++) a[k] = *((volatile double*)&g_acc[k]);
            double loss = 0.0;
            #pragma unroll
            for (int cls = 0; cls < 2; cls++) {
                double S_all = a[cls * 5 + 0];
                double S_out = a[cls * 5 + 1];
                double S_obj = a[cls * 5 + 2];
                double cOut  = a[cls * 5 + 3];
                double cObj  = a[cls * 5 + 4];
                double n_no  = (double)BB * HW - cOut;
                if (cObj > 0.0)
                    loss += LN2 * (S_obj / fmax(cObj, 1.0) +
                                   (S_all - S_out) / fmax(n_no, 1.0));
            }
            out[0] = (float)loss;
            #pragma unroll
            for (int k = 0; k < 10; k++) g_acc[k] = 0.0;
            g_ticket = 0u;
            __threadfence();
        }
    }
}

// ------------------------------------------------------------------
extern "C" void kernel_launch(void* const* d_in, const int* in_sizes, int n_in,
                              void* d_out, int out_size) {
    const float* pred = (const float*)d_in[0];
    const float* tgt  = (const float*)d_in[1];
    int nT = in_sizes[1] / 7;
    if (nT > MAXT) nT = MAXT;
    float* out = (float*)d_out;

    fused_kernel<<<nT + NSTR, NTHR>>>(pred, tgt, nT, out);
}